// round 3
// baseline (speedup 1.0000x reference)
#include <cuda_runtime.h>

#define MAX_NODES 100000
#define HID 64

// Scratch (allocation-free: __device__ globals)
__device__ float g_deg[MAX_NODES];
__device__ float g_dinv[MAX_NODES];
__device__ float g_h[(size_t)MAX_NODES * HID];     // h = X@W (pre-aggregation), reused for both layers
__device__ float g_out1[(size_t)MAX_NODES * HID];  // layer-1 aggregated output

// ---------------------------------------------------------------------------
// Degree pipeline: deg = 1 (self loop) + count of dst; dinv = deg^-0.5
// ---------------------------------------------------------------------------
__global__ void k_deg_init(int n) {
    int i = blockIdx.x * blockDim.x + threadIdx.x;
    if (i < n) g_deg[i] = 1.0f;
}

__global__ void k_deg_edge(const int* __restrict__ dst, int nE) {
    int e = blockIdx.x * blockDim.x + threadIdx.x;
    if (e < nE) atomicAdd(&g_deg[__ldg(&dst[e])], 1.0f);  // unused result -> REDG
}

__global__ void k_dinv(int n) {
    int i = blockIdx.x * blockDim.x + threadIdx.x;
    if (i < n) g_dinv[i] = rsqrtf(g_deg[i]);
}

// ---------------------------------------------------------------------------
// GEMM: h = act(A) @ W  [M x KDIM] @ [KDIM x 64]
// Epilogue: hout = h ;  aout = bias + h * dinv^2   (self-loop + bias folded in)
// Block tile 128x64, 256 threads, 8x4 register tile, BK=8.
// ---------------------------------------------------------------------------
template<int KDIM, bool RELU_IN>
__global__ void __launch_bounds__(256) k_gemm(const float* __restrict__ A,
                                              const float* __restrict__ W,
                                              const float* __restrict__ bias,
                                              float* __restrict__ hout,
                                              float* __restrict__ aout,
                                              int M)
{
    __shared__ float As[8][128];  // transposed: As[k][m]
    __shared__ float Bs[8][64];

    const int tx = threadIdx.x & 15;   // N direction (x4)
    const int ty = threadIdx.x >> 4;   // M direction (x8)
    const int row0 = blockIdx.x * 128;

    float acc[8][4];
#pragma unroll
    for (int i = 0; i < 8; i++)
#pragma unroll
        for (int j = 0; j < 4; j++) acc[i][j] = 0.0f;

    const int lrow = threadIdx.x >> 1;        // 0..127
    const int lcol = (threadIdx.x & 1) * 4;   // 0 or 4
    const int arow = min(row0 + lrow, M - 1); // clamp for partial last block

    for (int k0 = 0; k0 < KDIM; k0 += 8) {
        float4 av = *reinterpret_cast<const float4*>(A + (size_t)arow * KDIM + k0 + lcol);
        if (RELU_IN) {
            av.x = fmaxf(av.x, 0.0f); av.y = fmaxf(av.y, 0.0f);
            av.z = fmaxf(av.z, 0.0f); av.w = fmaxf(av.w, 0.0f);
        }
        As[lcol + 0][lrow] = av.x;
        As[lcol + 1][lrow] = av.y;
        As[lcol + 2][lrow] = av.z;
        As[lcol + 3][lrow] = av.w;
        if (threadIdx.x < 128) {
            const int bk = threadIdx.x >> 4;        // 0..7
            const int bj = (threadIdx.x & 15) * 4;  // 0..60
            *reinterpret_cast<float4*>(&Bs[bk][bj]) =
                *reinterpret_cast<const float4*>(W + (size_t)(k0 + bk) * HID + bj);
        }
        __syncthreads();
#pragma unroll
        for (int kk = 0; kk < 8; kk++) {
            float4 a0 = *reinterpret_cast<const float4*>(&As[kk][ty * 8]);
            float4 a1 = *reinterpret_cast<const float4*>(&As[kk][ty * 8 + 4]);
            float4 bv = *reinterpret_cast<const float4*>(&Bs[kk][tx * 4]);
            float a[8] = {a0.x, a0.y, a0.z, a0.w, a1.x, a1.y, a1.z, a1.w};
            float b[4] = {bv.x, bv.y, bv.z, bv.w};
#pragma unroll
            for (int i = 0; i < 8; i++)
#pragma unroll
                for (int j = 0; j < 4; j++) acc[i][j] = fmaf(a[i], b[j], acc[i][j]);
        }
        __syncthreads();
    }

    const float4 bvv = *reinterpret_cast<const float4*>(bias + tx * 4);
#pragma unroll
    for (int i = 0; i < 8; i++) {
        const int m = row0 + ty * 8 + i;
        if (m < M) {
            const float dv = g_dinv[m];
            const float d2 = dv * dv;
            const int off = m * HID + tx * 4;
            float4 hv = make_float4(acc[i][0], acc[i][1], acc[i][2], acc[i][3]);
            *reinterpret_cast<float4*>(hout + off) = hv;
            float4 ov = make_float4(bvv.x + hv.x * d2, bvv.y + hv.y * d2,
                                    bvv.z + hv.z * d2, bvv.w + hv.w * d2);
            *reinterpret_cast<float4*>(aout + off) = ov;
        }
    }
}

// ---------------------------------------------------------------------------
// Edge aggregation: out[dst] += h[src] * dinv[src] * dinv[dst]
// 16 lanes per edge; one LDG.128 gather + 4 scalar REDG.ADD.F32 per lane.
// ---------------------------------------------------------------------------
__global__ void __launch_bounds__(256) k_edge_agg(const int* __restrict__ src,
                                                  const int* __restrict__ dst,
                                                  const float* __restrict__ h,
                                                  float* __restrict__ out,
                                                  int nE)
{
    int gid = blockIdx.x * blockDim.x + threadIdx.x;
    int e = gid >> 4;
    if (e >= nE) return;
    int l = gid & 15;

    int s = __ldg(&src[e]);
    int d = __ldg(&dst[e]);
    float c = __ldg(&g_dinv[s]) * __ldg(&g_dinv[d]);

    const float4 v = __ldg(reinterpret_cast<const float4*>(h + (size_t)s * HID) + l);
    float* p = out + (size_t)d * HID + l * 4;
    atomicAdd(p + 0, v.x * c);
    atomicAdd(p + 1, v.y * c);
    atomicAdd(p + 2, v.z * c);
    atomicAdd(p + 3, v.w * c);
}

// ---------------------------------------------------------------------------
// Launch: deg -> dinv -> GEMM1(+init out1) -> edges -> GEMM2(+init out) -> edges
// ---------------------------------------------------------------------------
extern "C" void kernel_launch(void* const* d_in, const int* in_sizes, int n_in,
                              void* d_out, int out_size)
{
    const float* x  = (const float*)d_in[0];
    const int*   ei = (const int*)d_in[1];    // edge_index is int32 (JAX x64 disabled)
    const float* W1 = (const float*)d_in[2];
    const float* b1 = (const float*)d_in[3];
    const float* W2 = (const float*)d_in[4];
    const float* b2 = (const float*)d_in[5];
    float* out = (float*)d_out;

    const int n  = in_sizes[0] / 128;
    const int nE = in_sizes[1] / 2;
    const int* src = ei;
    const int* dst = ei + nE;

    float *h = nullptr, *out1 = nullptr;
    cudaGetSymbolAddress((void**)&h, g_h);
    cudaGetSymbolAddress((void**)&out1, g_out1);

    const int nb_nodes = (n + 255) / 256;
    const int nb_edges = (nE + 255) / 256;
    const long long agg_threads = (long long)nE * 16;
    const int nb_agg = (int)((agg_threads + 255) / 256);

    k_deg_init<<<nb_nodes, 256>>>(n);
    k_deg_edge<<<nb_edges, 256>>>(dst, nE);
    k_dinv<<<nb_nodes, 256>>>(n);

    // Layer 1
    k_gemm<128, false><<<(n + 127) / 128, 256>>>(x, W1, b1, h, out1, n);
    k_edge_agg<<<nb_agg, 256>>>(src, dst, h, out1, nE);

    // Layer 2 (ReLU fused into A-load; aggregation init written straight to d_out)
    k_gemm<64, true><<<(n + 127) / 128, 256>>>(out1, W2, b2, h, out, n);
    k_edge_agg<<<nb_agg, 256>>>(src, dst, h, out, nE);
}

// round 4
// speedup vs baseline: 1.6242x; 1.6242x over previous
#include <cuda_runtime.h>

#define MAX_NODES 100000
#define HID 64

// Scratch (allocation-free: __device__ globals)
__device__ float g_deg[MAX_NODES];
__device__ float g_dinv[MAX_NODES];
__device__ float g_h[(size_t)MAX_NODES * HID];     // h = X@W (pre-aggregation), reused for both layers
__device__ float g_out1[(size_t)MAX_NODES * HID];  // layer-1 aggregated output

// ---------------------------------------------------------------------------
// Degree pipeline: deg = 1 (self loop) + count of dst; dinv = deg^-0.5
// ---------------------------------------------------------------------------
__global__ void k_deg_init(int n) {
    int i = blockIdx.x * blockDim.x + threadIdx.x;
    if (i < n) g_deg[i] = 1.0f;
}

__global__ void k_deg_edge(const int* __restrict__ dst, int nE) {
    int e = blockIdx.x * blockDim.x + threadIdx.x;
    if (e < nE) atomicAdd(&g_deg[__ldg(&dst[e])], 1.0f);  // unused result -> REDG
}

__global__ void k_dinv(int n) {
    int i = blockIdx.x * blockDim.x + threadIdx.x;
    if (i < n) g_dinv[i] = rsqrtf(g_deg[i]);
}

// ---------------------------------------------------------------------------
// GEMM: h = act(A) @ W  [M x KDIM] @ [KDIM x 64]
// Epilogue: hout = h ;  aout = bias + h * dinv^2   (self-loop + bias folded in)
// Block tile 128x64, 256 threads, 8x4 register tile, BK=8.
// ---------------------------------------------------------------------------
template<int KDIM, bool RELU_IN>
__global__ void __launch_bounds__(256) k_gemm(const float* __restrict__ A,
                                              const float* __restrict__ W,
                                              const float* __restrict__ bias,
                                              float* __restrict__ hout,
                                              float* __restrict__ aout,
                                              int M)
{
    __shared__ float As[8][128];  // transposed: As[k][m]
    __shared__ float Bs[8][64];

    const int tx = threadIdx.x & 15;   // N direction (x4)
    const int ty = threadIdx.x >> 4;   // M direction (x8)
    const int row0 = blockIdx.x * 128;

    float acc[8][4];
#pragma unroll
    for (int i = 0; i < 8; i++)
#pragma unroll
        for (int j = 0; j < 4; j++) acc[i][j] = 0.0f;

    const int lrow = threadIdx.x >> 1;        // 0..127
    const int lcol = (threadIdx.x & 1) * 4;   // 0 or 4
    const int arow = min(row0 + lrow, M - 1); // clamp for partial last block

    for (int k0 = 0; k0 < KDIM; k0 += 8) {
        float4 av = *reinterpret_cast<const float4*>(A + (size_t)arow * KDIM + k0 + lcol);
        if (RELU_IN) {
            av.x = fmaxf(av.x, 0.0f); av.y = fmaxf(av.y, 0.0f);
            av.z = fmaxf(av.z, 0.0f); av.w = fmaxf(av.w, 0.0f);
        }
        As[lcol + 0][lrow] = av.x;
        As[lcol + 1][lrow] = av.y;
        As[lcol + 2][lrow] = av.z;
        As[lcol + 3][lrow] = av.w;
        if (threadIdx.x < 128) {
            const int bk = threadIdx.x >> 4;        // 0..7
            const int bj = (threadIdx.x & 15) * 4;  // 0..60
            *reinterpret_cast<float4*>(&Bs[bk][bj]) =
                *reinterpret_cast<const float4*>(W + (size_t)(k0 + bk) * HID + bj);
        }
        __syncthreads();
#pragma unroll
        for (int kk = 0; kk < 8; kk++) {
            float4 a0 = *reinterpret_cast<const float4*>(&As[kk][ty * 8]);
            float4 a1 = *reinterpret_cast<const float4*>(&As[kk][ty * 8 + 4]);
            float4 bv = *reinterpret_cast<const float4*>(&Bs[kk][tx * 4]);
            float a[8] = {a0.x, a0.y, a0.z, a0.w, a1.x, a1.y, a1.z, a1.w};
            float b[4] = {bv.x, bv.y, bv.z, bv.w};
#pragma unroll
            for (int i = 0; i < 8; i++)
#pragma unroll
                for (int j = 0; j < 4; j++) acc[i][j] = fmaf(a[i], b[j], acc[i][j]);
        }
        __syncthreads();
    }

    const float4 bvv = *reinterpret_cast<const float4*>(bias + tx * 4);
#pragma unroll
    for (int i = 0; i < 8; i++) {
        const int m = row0 + ty * 8 + i;
        if (m < M) {
            const float dv = g_dinv[m];
            const float d2 = dv * dv;
            const int off = m * HID + tx * 4;
            float4 hv = make_float4(acc[i][0], acc[i][1], acc[i][2], acc[i][3]);
            *reinterpret_cast<float4*>(hout + off) = hv;
            float4 ov = make_float4(bvv.x + hv.x * d2, bvv.y + hv.y * d2,
                                    bvv.z + hv.z * d2, bvv.w + hv.w * d2);
            *reinterpret_cast<float4*>(aout + off) = ov;
        }
    }
}

// ---------------------------------------------------------------------------
// Edge aggregation: out[dst] += h[src] * dinv[src] * dinv[dst]
// 16 lanes per edge. Leader lane loads (src, dst, dinv) once and broadcasts
// via shfl; each lane does one LDG.128 gather + one red.global.add.v4.f32.
// ---------------------------------------------------------------------------
__global__ void __launch_bounds__(256) k_edge_agg(const int* __restrict__ src,
                                                  const int* __restrict__ dst,
                                                  const float* __restrict__ h,
                                                  float* __restrict__ out,
                                                  int nE)
{
    const int gid  = blockIdx.x * blockDim.x + threadIdx.x;
    const int lane = threadIdx.x & 31;
    const int l    = lane & 15;               // position within the 16-lane group
    const int lead = lane & 16;               // leader lane id (0 or 16)
    const int e    = gid >> 4;
    const int ec   = min(e, nE - 1);          // clamped: all lanes join the shfl
    const bool valid = (e < nE);

    int s = 0, d = 0;
    float c = 0.0f;
    if (l == 0) {
        s = __ldg(&src[ec]);
        d = __ldg(&dst[ec]);
        c = __ldg(&g_dinv[s]) * __ldg(&g_dinv[d]);
    }
    s = __shfl_sync(0xffffffffu, s, lead);
    d = __shfl_sync(0xffffffffu, d, lead);
    c = __shfl_sync(0xffffffffu, c, lead);

    const float4 v = __ldg(reinterpret_cast<const float4*>(h + (size_t)s * HID) + l);
    if (valid) {
        float* p = out + (size_t)d * HID + l * 4;
        asm volatile("red.global.add.v4.f32 [%0], {%1,%2,%3,%4};"
                     :: "l"(p), "f"(v.x * c), "f"(v.y * c), "f"(v.z * c), "f"(v.w * c)
                     : "memory");
    }
}

// ---------------------------------------------------------------------------
// Launch: deg -> dinv -> GEMM1(+init out1) -> edges -> GEMM2(+init out) -> edges
// ---------------------------------------------------------------------------
extern "C" void kernel_launch(void* const* d_in, const int* in_sizes, int n_in,
                              void* d_out, int out_size)
{
    const float* x  = (const float*)d_in[0];
    const int*   ei = (const int*)d_in[1];    // edge_index is int32 (JAX x64 disabled)
    const float* W1 = (const float*)d_in[2];
    const float* b1 = (const float*)d_in[3];
    const float* W2 = (const float*)d_in[4];
    const float* b2 = (const float*)d_in[5];
    float* out = (float*)d_out;

    const int n  = in_sizes[0] / 128;
    const int nE = in_sizes[1] / 2;
    const int* src = ei;
    const int* dst = ei + nE;

    float *h = nullptr, *out1 = nullptr;
    cudaGetSymbolAddress((void**)&h, g_h);
    cudaGetSymbolAddress((void**)&out1, g_out1);

    const int nb_nodes = (n + 255) / 256;
    const int nb_edges = (nE + 255) / 256;
    const long long agg_threads = (long long)nE * 16;
    const int nb_agg = (int)((agg_threads + 255) / 256);

    k_deg_init<<<nb_nodes, 256>>>(n);
    k_deg_edge<<<nb_edges, 256>>>(dst, nE);
    k_dinv<<<nb_nodes, 256>>>(n);

    // Layer 1
    k_gemm<128, false><<<(n + 127) / 128, 256>>>(x, W1, b1, h, out1, n);
    k_edge_agg<<<nb_agg, 256>>>(src, dst, h, out1, nE);

    // Layer 2 (ReLU fused into A-load; aggregation init written straight to d_out)
    k_gemm<64, true><<<(n + 127) / 128, 256>>>(out1, W2, b2, h, out, n);
    k_edge_agg<<<nb_agg, 256>>>(src, dst, h, out, nE);
}

// round 5
// speedup vs baseline: 2.2351x; 1.3761x over previous
#include <cuda_runtime.h>

#define MAX_NODES 100000
#define MAX_EDGES 1250000
#define HID 64

// Scratch (allocation-free: __device__ globals)
__device__ int   g_cnt[MAX_NODES];       // in-degree (without self loop)
__device__ int   g_rowstart[MAX_NODES];  // CSR row start (exclusive scan of cnt)
__device__ int   g_cursor[MAX_NODES];    // scatter cursors
__device__ int   g_blocksum[256];
__device__ float g_dinv[MAX_NODES];
__device__ int   g_psrc[MAX_EDGES];      // src ids sorted by dst
__device__ float g_h[(size_t)MAX_NODES * HID];
__device__ float g_out1[(size_t)MAX_NODES * HID];

// ---------------------------------------------------------------------------
// CSR build: count -> scan(3 kernels) -> finish(dinv+cursor) -> scatter
// ---------------------------------------------------------------------------
__global__ void k_zero_cnt(int n) {
    int i = blockIdx.x * blockDim.x + threadIdx.x;
    if (i < n) g_cnt[i] = 0;
}

__global__ void k_count(const int* __restrict__ dst, int nE) {
    int e = blockIdx.x * blockDim.x + threadIdx.x;
    if (e < nE) atomicAdd(&g_cnt[__ldg(&dst[e])], 1);
}

// Per-block exclusive scan (1024 elems/block) + block totals
__global__ void __launch_bounds__(1024) k_scan_block(int n) {
    __shared__ int sh[1024];
    const int t = threadIdx.x;
    const int i = blockIdx.x * 1024 + t;
    int v = (i < n) ? g_cnt[i] : 0;
    sh[t] = v;
    __syncthreads();
#pragma unroll
    for (int off = 1; off < 1024; off <<= 1) {
        int add = (t >= off) ? sh[t - off] : 0;
        __syncthreads();
        sh[t] += add;
        __syncthreads();
    }
    if (i < n) g_rowstart[i] = sh[t] - v;            // exclusive within block
    if (t == 1023) g_blocksum[blockIdx.x] = sh[t];   // block total
}

// Single-block exclusive scan of block totals (nb <= 128)
__global__ void __launch_bounds__(128) k_scan_tops(int nb) {
    __shared__ int sh[128];
    const int t = threadIdx.x;
    int v = (t < nb) ? g_blocksum[t] : 0;
    sh[t] = v;
    __syncthreads();
#pragma unroll
    for (int off = 1; off < 128; off <<= 1) {
        int add = (t >= off) ? sh[t - off] : 0;
        __syncthreads();
        sh[t] += add;
        __syncthreads();
    }
    if (t < nb) g_blocksum[t] = sh[t] - v;           // exclusive tops, in place
}

__global__ void k_scan_finish(int n) {
    int i = blockIdx.x * blockDim.x + threadIdx.x;
    if (i < n) {
        int rs = g_rowstart[i] + g_blocksum[i >> 10];
        g_rowstart[i] = rs;
        g_cursor[i]   = rs;
        g_dinv[i]     = rsqrtf((float)g_cnt[i] + 1.0f);  // +1 self loop
    }
}

__global__ void k_scatter(const int* __restrict__ src, const int* __restrict__ dst, int nE) {
    int e = blockIdx.x * blockDim.x + threadIdx.x;
    if (e < nE) {
        int d = __ldg(&dst[e]);
        int pos = atomicAdd(&g_cursor[d], 1);
        g_psrc[pos] = __ldg(&src[e]);
    }
}

// ---------------------------------------------------------------------------
// GEMM: h = act(A) @ W  [M x KDIM] @ [KDIM x 64]
// Epilogue: hout = h ;  aout = bias + h * dinv^2   (self-loop + bias folded in)
// ---------------------------------------------------------------------------
template<int KDIM, bool RELU_IN>
__global__ void __launch_bounds__(256) k_gemm(const float* __restrict__ A,
                                              const float* __restrict__ W,
                                              const float* __restrict__ bias,
                                              float* __restrict__ hout,
                                              float* __restrict__ aout,
                                              int M)
{
    __shared__ float As[8][128];
    __shared__ float Bs[8][64];

    const int tx = threadIdx.x & 15;
    const int ty = threadIdx.x >> 4;
    const int row0 = blockIdx.x * 128;

    float acc[8][4];
#pragma unroll
    for (int i = 0; i < 8; i++)
#pragma unroll
        for (int j = 0; j < 4; j++) acc[i][j] = 0.0f;

    const int lrow = threadIdx.x >> 1;
    const int lcol = (threadIdx.x & 1) * 4;
    const int arow = min(row0 + lrow, M - 1);

    for (int k0 = 0; k0 < KDIM; k0 += 8) {
        float4 av = *reinterpret_cast<const float4*>(A + (size_t)arow * KDIM + k0 + lcol);
        if (RELU_IN) {
            av.x = fmaxf(av.x, 0.0f); av.y = fmaxf(av.y, 0.0f);
            av.z = fmaxf(av.z, 0.0f); av.w = fmaxf(av.w, 0.0f);
        }
        As[lcol + 0][lrow] = av.x;
        As[lcol + 1][lrow] = av.y;
        As[lcol + 2][lrow] = av.z;
        As[lcol + 3][lrow] = av.w;
        if (threadIdx.x < 128) {
            const int bk = threadIdx.x >> 4;
            const int bj = (threadIdx.x & 15) * 4;
            *reinterpret_cast<float4*>(&Bs[bk][bj]) =
                *reinterpret_cast<const float4*>(W + (size_t)(k0 + bk) * HID + bj);
        }
        __syncthreads();
#pragma unroll
        for (int kk = 0; kk < 8; kk++) {
            float4 a0 = *reinterpret_cast<const float4*>(&As[kk][ty * 8]);
            float4 a1 = *reinterpret_cast<const float4*>(&As[kk][ty * 8 + 4]);
            float4 bv = *reinterpret_cast<const float4*>(&Bs[kk][tx * 4]);
            float a[8] = {a0.x, a0.y, a0.z, a0.w, a1.x, a1.y, a1.z, a1.w};
            float b[4] = {bv.x, bv.y, bv.z, bv.w};
#pragma unroll
            for (int i = 0; i < 8; i++)
#pragma unroll
                for (int j = 0; j < 4; j++) acc[i][j] = fmaf(a[i], b[j], acc[i][j]);
        }
        __syncthreads();
    }

    const float4 bvv = *reinterpret_cast<const float4*>(bias + tx * 4);
#pragma unroll
    for (int i = 0; i < 8; i++) {
        const int m = row0 + ty * 8 + i;
        if (m < M) {
            const float dv = g_dinv[m];
            const float d2 = dv * dv;
            const int off = m * HID + tx * 4;
            float4 hv = make_float4(acc[i][0], acc[i][1], acc[i][2], acc[i][3]);
            *reinterpret_cast<float4*>(hout + off) = hv;
            float4 ov = make_float4(bvv.x + hv.x * d2, bvv.y + hv.y * d2,
                                    bvv.z + hv.z * d2, bvv.w + hv.w * d2);
            *reinterpret_cast<float4*>(aout + off) = ov;
        }
    }
}

// ---------------------------------------------------------------------------
// Pull-mode aggregation over CSR: out[d] += dinv[d] * sum_{s in N(d)} dinv[s]*h[s]
// 16 lanes per dst node, two independent half-segment chains for MLP.
// out already holds init = bias + h[d]*dinv[d]^2 (GEMM epilogue).
// ---------------------------------------------------------------------------
__global__ void __launch_bounds__(256) k_node_agg(const float* __restrict__ h,
                                                   float* __restrict__ out,
                                                   int n)
{
    const int gid  = blockIdx.x * blockDim.x + threadIdx.x;
    const int node = gid >> 4;
    const int l    = gid & 15;
    if (node >= n) return;

    const int start = __ldg(&g_rowstart[node]);
    const int cn    = __ldg(&g_cnt[node]);
    const int half  = cn >> 1;

    float4 acc0 = make_float4(0.f, 0.f, 0.f, 0.f);
    float4 acc1 = make_float4(0.f, 0.f, 0.f, 0.f);

    const int a0 = start;
    const int b0 = start + half;
    for (int k = 0; k < half; k++) {
        const int sa = __ldg(&g_psrc[a0 + k]);
        const int sb = __ldg(&g_psrc[b0 + k]);
        const float wa = __ldg(&g_dinv[sa]);
        const float wb = __ldg(&g_dinv[sb]);
        const float4 va = __ldg(reinterpret_cast<const float4*>(h + (size_t)sa * HID) + l);
        const float4 vb = __ldg(reinterpret_cast<const float4*>(h + (size_t)sb * HID) + l);
        acc0.x = fmaf(wa, va.x, acc0.x); acc1.x = fmaf(wb, vb.x, acc1.x);
        acc0.y = fmaf(wa, va.y, acc0.y); acc1.y = fmaf(wb, vb.y, acc1.y);
        acc0.z = fmaf(wa, va.z, acc0.z); acc1.z = fmaf(wb, vb.z, acc1.z);
        acc0.w = fmaf(wa, va.w, acc0.w); acc1.w = fmaf(wb, vb.w, acc1.w);
    }
    if (cn & 1) {
        const int s = __ldg(&g_psrc[start + cn - 1]);
        const float w = __ldg(&g_dinv[s]);
        const float4 v = __ldg(reinterpret_cast<const float4*>(h + (size_t)s * HID) + l);
        acc0.x = fmaf(w, v.x, acc0.x);
        acc0.y = fmaf(w, v.y, acc0.y);
        acc0.z = fmaf(w, v.z, acc0.z);
        acc0.w = fmaf(w, v.w, acc0.w);
    }

    const float dd = __ldg(&g_dinv[node]);
    float* p = out + (size_t)node * HID + l * 4;
    float4 o = *reinterpret_cast<float4*>(p);
    o.x += dd * (acc0.x + acc1.x);
    o.y += dd * (acc0.y + acc1.y);
    o.z += dd * (acc0.z + acc1.z);
    o.w += dd * (acc0.w + acc1.w);
    *reinterpret_cast<float4*>(p) = o;
}

// ---------------------------------------------------------------------------
// Launch
// ---------------------------------------------------------------------------
extern "C" void kernel_launch(void* const* d_in, const int* in_sizes, int n_in,
                              void* d_out, int out_size)
{
    const float* x  = (const float*)d_in[0];
    const int*   ei = (const int*)d_in[1];   // edge_index is int32
    const float* W1 = (const float*)d_in[2];
    const float* b1 = (const float*)d_in[3];
    const float* W2 = (const float*)d_in[4];
    const float* b2 = (const float*)d_in[5];
    float* out = (float*)d_out;

    const int n  = in_sizes[0] / 128;
    const int nE = in_sizes[1] / 2;
    const int* src = ei;
    const int* dst = ei + nE;

    float *h = nullptr, *out1 = nullptr;
    cudaGetSymbolAddress((void**)&h, g_h);
    cudaGetSymbolAddress((void**)&out1, g_out1);

    const int nb_nodes = (n + 255) / 256;
    const int nb_edges = (nE + 255) / 256;
    const int nb_scan  = (n + 1023) / 1024;          // <= 128 for n <= 131072
    const int nb_agg   = (n * 16 + 255) / 256;

    // CSR build + dinv
    k_zero_cnt<<<nb_nodes, 256>>>(n);
    k_count<<<nb_edges, 256>>>(dst, nE);
    k_scan_block<<<nb_scan, 1024>>>(n);
    k_scan_tops<<<1, 128>>>(nb_scan);
    k_scan_finish<<<nb_nodes, 256>>>(n);
    k_scatter<<<nb_edges, 256>>>(src, dst, nE);

    // Layer 1
    k_gemm<128, false><<<(n + 127) / 128, 256>>>(x, W1, b1, h, out1, n);
    k_node_agg<<<nb_agg, 256>>>(h, out1, n);

    // Layer 2 (ReLU fused into A-load; init written straight to d_out)
    k_gemm<64, true><<<(n + 127) / 128, 256>>>(out1, W2, b2, h, out, n);
    k_node_agg<<<nb_agg, 256>>>(h, out, n);
}